// round 9
// baseline (speedup 1.0000x reference)
#include <cuda_runtime.h>
#include <cuda_bf16.h>
#include <cstdint>

#define BATCH   4
#define SEQL    4096
#define DMODEL  2048
#define HALF    32
#define N2      64
#define MTOT    (BATCH*SEQL)
#define CHUNK   64
#define NCHUNK  (SEQL/CHUNK)

// ---------------- scratch ----------------
__device__ __nv_bfloat16 g_W1h[N2 * DMODEL];   // [j][d]  B operand of GEMM1
__device__ __nv_bfloat16 g_W1l[N2 * DMODEL];
__device__ __nv_bfloat16 g_W2h[DMODEL * N2];   // [d][j]  B operand of GEMM2
__device__ __nv_bfloat16 g_W2l[DMODEL * N2];
__device__ float g_Bu[MTOT * N2];
__device__ __nv_bfloat16 g_Xh[MTOT * N2];      // corrected X, bf16 hi
__device__ __nv_bfloat16 g_Xl[MTOT * N2];      // corrected X, bf16 lo
__device__ float g_carry[BATCH * NCHUNK * N2];
__device__ float g_pref [BATCH * NCHUNK * N2];
__device__ float g_par[192];

// ---------------- helpers ----------------
__device__ __forceinline__ uint32_t smem_u32(const void* p) {
    uint32_t a;
    asm("{ .reg .u64 t; cvta.to.shared.u64 t, %1; cvt.u32.u64 %0, t; }"
        : "=r"(a) : "l"(p));
    return a;
}

__device__ __forceinline__ void cvt_hl(float x, uint16_t& h, uint16_t& l) {
    __nv_bfloat16 hb = __float2bfloat16_rn(x);
    float r = x - __bfloat162float(hb);
    __nv_bfloat16 lb = __float2bfloat16_rn(r);
    h = *(uint16_t*)&hb;
    l = *(uint16_t*)&lb;
}

// paired split: 2 floats -> packed bf16x2 hi + packed bf16x2 lo
__device__ __forceinline__ void cvt_hl2(float x0, float x1,
                                        uint32_t& h, uint32_t& l) {
    uint32_t hp;
    asm("cvt.rn.bf16x2.f32 %0, %1, %2;" : "=r"(hp) : "f"(x1), "f"(x0));
    float f0 = __uint_as_float(hp << 16);
    float f1 = __uint_as_float(hp & 0xffff0000u);
    float r0 = x0 - f0;
    float r1 = x1 - f1;
    asm("cvt.rn.bf16x2.f32 %0, %1, %2;" : "=r"(l) : "f"(r1), "f"(r0));
    h = hp;
}

__device__ __forceinline__ void cvt8(const float4& v0, const float4& v1,
                                     uint4& h, uint4& l) {
    cvt_hl2(v0.x, v0.y, h.x, l.x);
    cvt_hl2(v0.z, v0.w, h.y, l.y);
    cvt_hl2(v1.x, v1.y, h.z, l.z);
    cvt_hl2(v1.z, v1.w, h.w, l.w);
}

__device__ __forceinline__ void mma16816(float* c, const uint32_t* a,
                                         const uint32_t* b) {
    asm volatile(
        "mma.sync.aligned.m16n8k16.row.col.f32.bf16.bf16.f32 "
        "{%0,%1,%2,%3}, {%4,%5,%6,%7}, {%8,%9}, {%0,%1,%2,%3};"
        : "+f"(c[0]), "+f"(c[1]), "+f"(c[2]), "+f"(c[3])
        : "r"(a[0]), "r"(a[1]), "r"(a[2]), "r"(a[3]), "r"(b[0]), "r"(b[1]));
}

__device__ __forceinline__ void ldsm4(uint32_t addr, uint32_t* r) {
    asm volatile(
        "ldmatrix.sync.aligned.m8n8.x4.shared.b16 {%0,%1,%2,%3}, [%4];"
        : "=r"(r[0]), "=r"(r[1]), "=r"(r[2]), "=r"(r[3]) : "r"(addr));
}

// Panels: kp holds 8 k-values; 16B per row; XOR(row, kp) swizzle.
__device__ __forceinline__ uint32_t lmoff(int p, int rb, int lane, int psz) {
    int pp = p + (lane >> 4);
    int row = rb + (lane & 15);
    return (uint32_t)(pp * psz + (((row ^ (pp & 7)) << 4)));
}

// ---------------- setup ----------------
__global__ void k_params(const float* __restrict__ Lur,
                         const float* __restrict__ Lim,
                         const float* __restrict__ logD) {
    int n = threadIdx.x;
    if (n >= HALF) return;
    float x   = Lur[n];
    float sp  = (x > 20.f) ? x : log1pf(expf(x));
    float lre = -(sp + 1e-4f + 0.01f);
    float lim = Lim[n];
    float dt  = expf(logD[n]);
    float ar = lre * dt, ai = lim * dt;
    float er = expf(ar);
    float lbr = er * cosf(ai);
    float lbi = er * sinf(ai);
    float den = lre * lre + lim * lim;
    float nr = lbr - 1.f, ni = lbi;
    float sre = (nr * lre + ni * lim) / den;
    float sim = (ni * lre - nr * lim) / den;
    float er64 = expf((float)CHUNK * ar);
    float a64  = (float)CHUNK * ai;
    float lbSr = er64 * cosf(a64);
    float lbSi = er64 * sinf(a64);
    g_par[n]       = lbr;  g_par[32 + n]  = lbi;
    g_par[64 + n]  = lbSr; g_par[96 + n]  = lbSi;
    g_par[128 + n] = sre;  g_par[160 + n] = sim;
}

__global__ void k_w1(const float* __restrict__ Bre, const float* __restrict__ Bim) {
    for (int idx = blockIdx.x * blockDim.x + threadIdx.x; idx < N2 * DMODEL;
         idx += gridDim.x * blockDim.x) {
        int j = idx >> 11;
        int d = idx & 2047;
        int n = j & 31;
        float sre = g_par[128 + n], sim = g_par[160 + n];
        float br = Bre[n * DMODEL + d], bi = Bim[n * DMODEL + d];
        float v = (j < 32) ? (sre * br - sim * bi) : (sre * bi + sim * br);
        uint16_t h, l;
        cvt_hl(v, h, l);
        g_W1h[idx] = *(__nv_bfloat16*)&h;
        g_W1l[idx] = *(__nv_bfloat16*)&l;
    }
}

__global__ void k_w2(const float* __restrict__ Cre, const float* __restrict__ Cim) {
    for (int idx = blockIdx.x * blockDim.x + threadIdx.x; idx < DMODEL * N2;
         idx += gridDim.x * blockDim.x) {
        int d = idx >> 6;
        int j = idx & 63;
        float v = (j < 32) ? (2.f * Cre[d * HALF + j])
                           : (-2.f * Cim[d * HALF + (j - 32)]);
        uint16_t h, l;
        cvt_hl(v, h, l);
        g_W2h[idx] = *(__nv_bfloat16*)&h;
        g_W2l[idx] = *(__nv_bfloat16*)&l;
    }
}

// ---------------- GEMM1: Bu = u @ W1^T  (bf16x3 HMMA, LDSM, 2-stage) ----------------
// 256 thr, BM=128, BN=64, K_TILE=64 (8 panels), grid 128; warp = m32 x n32.
// Stage: Ah 16K | Al 16K | Bh 8K | Bl 8K (48 KB), 2 stages. Fragment dbl-buffer.
#define G1_STAGE 49152
__global__ __launch_bounds__(256) void k_gemm1(const float* __restrict__ u) {
    extern __shared__ char smem[];
    int tid = threadIdx.x;
    int lane = tid & 31, g = lane >> 2, tig = lane & 3;
    int w = tid >> 5, wm = w >> 1, wn = w & 1;
    int m0 = blockIdx.x * 128;

    float acc[2][4][4];
    #pragma unroll
    for (int mt = 0; mt < 2; ++mt)
        #pragma unroll
        for (int f = 0; f < 4; ++f)
            #pragma unroll
            for (int i = 0; i < 4; ++i) acc[mt][f][i] = 0.f;

    uint32_t oAh0[4], oAh1[4], oAl0[4], oAl1[4];
    uint32_t oBh0[4], oBh1[4], oBl0[4], oBl1[4];
    #pragma unroll
    for (int ks = 0; ks < 4; ++ks) {
        int p = ks * 2;
        oAh0[ks] =         lmoff(p, wm * 32,      lane, 2048);
        oAh1[ks] =         lmoff(p, wm * 32 + 16, lane, 2048);
        oAl0[ks] = 16384 + lmoff(p, wm * 32,      lane, 2048);
        oAl1[ks] = 16384 + lmoff(p, wm * 32 + 16, lane, 2048);
        oBh0[ks] = 32768 + lmoff(p, wn * 32,      lane, 1024);
        oBh1[ks] = 32768 + lmoff(p, wn * 32 + 16, lane, 1024);
        oBl0[ks] = 40960 + lmoff(p, wn * 32,      lane, 1024);
        oBl1[ks] = 40960 + lmoff(p, wn * 32 + 16, lane, 1024);
    }
    uint32_t sb0 = smem_u32(smem);
    uint32_t sb1 = sb0 + G1_STAGE;

    float4 ru[4][2];
    uint4 rwh[2], rwl[2];

    #define G1_LDG(kb)                                                        \
        _Pragma("unroll")                                                     \
        for (int i = 0; i < 4; ++i) {                                         \
            int task = tid + 256 * i;                                         \
            int row = task >> 3, kp = task & 7;                               \
            const float* s = u + (size_t)(m0 + row) * DMODEL + (kb) + kp * 8; \
            ru[i][0] = *(const float4*)s;                                     \
            ru[i][1] = *(const float4*)(s + 4);                               \
        }                                                                     \
        _Pragma("unroll")                                                     \
        for (int i = 0; i < 2; ++i) {                                         \
            int task = tid + 256 * i;                                         \
            int n = task >> 3, kp = task & 7;                                 \
            size_t off = ((size_t)n * DMODEL + (kb) + kp * 8) * 2;            \
            rwh[i] = *(const uint4*)((const char*)g_W1h + off);               \
            rwl[i] = *(const uint4*)((const char*)g_W1l + off);               \
        }

    #define G1_STS(sbase)                                                     \
        _Pragma("unroll")                                                     \
        for (int i = 0; i < 4; ++i) {                                         \
            int task = tid + 256 * i;                                         \
            int row = task >> 3, kp = task & 7;                               \
            uint4 h, l;                                                       \
            cvt8(ru[i][0], ru[i][1], h, l);                                   \
            int off = kp * 2048 + ((row ^ kp) << 4);                          \
            *(uint4*)((sbase) + off) = h;                                     \
            *(uint4*)((sbase) + 16384 + off) = l;                             \
        }                                                                     \
        _Pragma("unroll")                                                     \
        for (int i = 0; i < 2; ++i) {                                         \
            int task = tid + 256 * i;                                         \
            int n = task >> 3, kp = task & 7;                                 \
            int off = kp * 1024 + ((n ^ kp) << 4);                            \
            *(uint4*)((sbase) + 32768 + off) = rwh[i];                        \
            *(uint4*)((sbase) + 40960 + off) = rwl[i];                        \
        }

    #define G1_LDF(b, ks)                                                     \
        ldsm4(sb + oAh0[ks], fah0[b]);                                        \
        ldsm4(sb + oAh1[ks], fah1[b]);                                        \
        ldsm4(sb + oAl0[ks], fal0[b]);                                        \
        ldsm4(sb + oAl1[ks], fal1[b]);                                        \
        ldsm4(sb + oBh0[ks], fbh[b]);                                         \
        ldsm4(sb + oBh1[ks], fbh[b] + 4);                                     \
        ldsm4(sb + oBl0[ks], fbl[b]);                                         \
        ldsm4(sb + oBl1[ks], fbl[b] + 4);

    G1_LDG(0);
    G1_STS(smem);
    G1_LDG(64);
    __syncthreads();

    for (int kt = 0; kt < DMODEL / 64; ++kt) {
        if (kt + 1 < DMODEL / 64) {
            char* nst = smem + ((kt + 1) & 1) * G1_STAGE;
            G1_STS(nst);
        }
        if (kt + 2 < DMODEL / 64) {
            G1_LDG((kt + 2) * 64);
        }
        uint32_t sb = (kt & 1) ? sb1 : sb0;
        uint32_t fah0[2][4], fah1[2][4], fal0[2][4], fal1[2][4];
        uint32_t fbh[2][8], fbl[2][8];
        G1_LDF(0, 0);
        #pragma unroll
        for (int ks = 0; ks < 4; ++ks) {
            int cb = ks & 1;
            if (ks < 3) { G1_LDF(cb ^ 1, ks + 1); }
            #pragma unroll
            for (int f = 0; f < 4; ++f) {
                int q = (f >> 1) * 4 + (f & 1);
                uint32_t bfh[2] = { fbh[cb][q], fbh[cb][q + 2] };
                uint32_t bfl[2] = { fbl[cb][q], fbl[cb][q + 2] };
                mma16816(acc[0][f], fah0[cb], bfh);
                mma16816(acc[0][f], fah0[cb], bfl);
                mma16816(acc[0][f], fal0[cb], bfh);
                mma16816(acc[1][f], fah1[cb], bfh);
                mma16816(acc[1][f], fah1[cb], bfl);
                mma16816(acc[1][f], fal1[cb], bfh);
            }
        }
        __syncthreads();
    }
    #pragma unroll
    for (int mt = 0; mt < 2; ++mt) {
        int r0 = m0 + wm * 32 + mt * 16 + g;
        #pragma unroll
        for (int f = 0; f < 4; ++f) {
            int col = wn * 32 + f * 8 + 2 * tig;
            float* a = acc[mt][f];
            *(float2*)(g_Bu + (size_t)r0 * N2 + col)       = make_float2(a[0], a[1]);
            *(float2*)(g_Bu + (size_t)(r0 + 8) * N2 + col) = make_float2(a[2], a[3]);
        }
    }
    #undef G1_LDG
    #undef G1_STS
    #undef G1_LDF
}

// ---------------- scan phase 1 (prefetched) ----------------
__global__ void k_scan_local() {
    int w = (blockIdx.x * blockDim.x + threadIdx.x) >> 5;
    int lane = threadIdx.x & 31;
    int b = w >> 6, c = w & (NCHUNK - 1);
    float lbr = g_par[lane], lbi = g_par[32 + lane];
    float xr = 0.f, xi = 0.f;
    size_t base = ((size_t)b * SEQL + (size_t)c * CHUNK) * N2;
    float br = g_Bu[base + lane];
    float bi = g_Bu[base + 32 + lane];
    for (int i = 0; i < CHUNK; ++i) {
        size_t off = base + (size_t)i * N2;
        float nbr = 0.f, nbi = 0.f;
        if (i + 1 < CHUNK) {
            nbr = g_Bu[off + N2 + lane];
            nbi = g_Bu[off + N2 + 32 + lane];
        }
        float nr = fmaf(lbr, xr, fmaf(-lbi, xi, br));
        float ni = fmaf(lbr, xi, fmaf( lbi, xr, bi));
        g_Bu[off + lane]      = nr;
        g_Bu[off + 32 + lane] = ni;
        xr = nr; xi = ni;
        br = nbr; bi = nbi;
    }
    int co = (b * NCHUNK + c) * N2;
    g_carry[co + lane] = xr;
    g_carry[co + 32 + lane] = xi;
}

// ---------------- scan phase 2 ----------------
__global__ void k_scan_prefix() {
    int w = threadIdx.x >> 5;
    int lane = threadIdx.x & 31;
    float lbSr = g_par[64 + lane], lbSi = g_par[96 + lane];
    float Pr = 0.f, Pi = 0.f;
    for (int c = 0; c < NCHUNK; ++c) {
        int o = (w * NCHUNK + c) * N2;
        g_pref[o + lane] = Pr;
        g_pref[o + 32 + lane] = Pi;
        float cr = g_carry[o + lane];
        float ci = g_carry[o + 32 + lane];
        float nr = fmaf(lbSr, Pr, fmaf(-lbSi, Pi, cr));
        float ni = fmaf(lbSr, Pi, fmaf( lbSi, Pr, ci));
        Pr = nr; Pi = ni;
    }
}

// ---------------- scan phase 3: fixup + emit bf16 hi/lo X ----------------
__global__ void k_scan_fix() {
    int w = (blockIdx.x * blockDim.x + threadIdx.x) >> 5;
    int lane = threadIdx.x & 31;
    int b = w >> 6, c = w & (NCHUNK - 1);
    float lbr = g_par[lane], lbi = g_par[32 + lane];
    int po = (b * NCHUNK + c) * N2;
    float Pr = g_pref[po + lane], Pi = g_pref[po + 32 + lane];
    float pr = lbr, pi = lbi;
    size_t mbase = (size_t)b * SEQL + (size_t)c * CHUNK;
    size_t base = mbase * N2;
    float br = g_Bu[base + lane];
    float bi = g_Bu[base + 32 + lane];
    for (int i = 0; i < CHUNK; ++i) {
        size_t off = base + (size_t)i * N2;
        float nbr = 0.f, nbi = 0.f;
        if (i + 1 < CHUNK) {
            nbr = g_Bu[off + N2 + lane];
            nbi = g_Bu[off + N2 + 32 + lane];
        }
        float xr = fmaf(pr, Pr, fmaf(-pi, Pi, br));
        float xi = fmaf(pr, Pi, fmaf( pi, Pr, bi));
        uint16_t hr, lr, hi_, li_;
        cvt_hl(xr, hr, lr);
        cvt_hl(xi, hi_, li_);
        size_t ro = (mbase + i) * N2;
        g_Xh[ro + lane]      = *(__nv_bfloat16*)&hr;
        g_Xh[ro + 32 + lane] = *(__nv_bfloat16*)&hi_;
        g_Xl[ro + lane]      = *(__nv_bfloat16*)&lr;
        g_Xl[ro + 32 + lane] = *(__nv_bfloat16*)&li_;
        float npr = pr * lbr - pi * lbi;
        float npi = pr * lbi + pi * lbr;
        pr = npr; pi = npi;
        br = nbr; bi = nbi;
    }
}

// ---------------- GEMM2: y = X @ W2 + D.u  (N-sweep, B double-buffered) ----------
// 256 thr, BM=128, grid 128 (one block per M-slab); loop over 16 N-tiles of 128.
// Smem: Ah 16K | Al 16K | B stage0 (h16K,l16K) | B stage1 (h16K,l16K) = 96 KB.
__global__ __launch_bounds__(256) void k_gemm2(const float* __restrict__ u,
                                               const float* __restrict__ Dv,
                                               float* __restrict__ y) {
    extern __shared__ char smem[];
    char* pAh = smem;
    char* pAl = smem + 16384;
    char* pB0 = smem + 32768;     // stage 0: h at +0, l at +16384
    char* pB1 = smem + 65536;     // stage 1
    int tid = threadIdx.x;
    int lane = tid & 31, g = lane >> 2, tig = lane & 3;
    int w = tid >> 5, wm = w >> 1, wn = w & 1;
    int m0 = blockIdx.x * 128;

    // stage A = preconverted X bf16 hi/lo (once per block)
    #pragma unroll
    for (int i = 0; i < 4; ++i) {
        int task = tid + 256 * i;
        int row = task >> 3, kp = task & 7;
        size_t goff = ((size_t)(m0 + row) * N2 + kp * 8) * 2;
        int off = kp * 2048 + ((row ^ kp) << 4);
        *(uint4*)(pAh + off) = *(const uint4*)((const char*)g_Xh + goff);
        *(uint4*)(pAl + off) = *(const uint4*)((const char*)g_Xl + goff);
    }

    uint4 rwh[4], rwl[4];
    #define G2_LDGB(nt)                                                       \
        _Pragma("unroll")                                                     \
        for (int i = 0; i < 4; ++i) {                                         \
            int task = tid + 256 * i;                                         \
            int n = task >> 3, kp = task & 7;                                 \
            size_t goff = ((size_t)((nt) * 128 + n) * N2 + kp * 8) * 2;       \
            rwh[i] = *(const uint4*)((const char*)g_W2h + goff);              \
            rwl[i] = *(const uint4*)((const char*)g_W2l + goff);              \
        }
    #define G2_STSB(base)                                                     \
        _Pragma("unroll")                                                     \
        for (int i = 0; i < 4; ++i) {                                         \
            int task = tid + 256 * i;                                         \
            int n = task >> 3, kp = task & 7;                                 \
            int off = kp * 2048 + ((n ^ kp) << 4);                            \
            *(uint4*)((base) + off) = rwh[i];                                 \
            *(uint4*)((base) + 16384 + off) = rwl[i];                         \
        }

    G2_LDGB(0);
    G2_STSB(pB0);
    G2_LDGB(1);
    __syncthreads();

    uint32_t aAh = smem_u32(pAh), aAl = smem_u32(pAl);
    uint32_t b0 = smem_u32(pB0), b1 = smem_u32(pB1);

    for (int nt = 0; nt < 16; ++nt) {
        if (nt + 1 < 16) {
            char* nst = (nt & 1) ? pB0 : pB1;
            G2_STSB(nst);
        }
        if (nt + 2 < 16) {
            G2_LDGB(nt + 2);
        }
        __syncthreads();
        uint32_t aBh = (nt & 1) ? b1 : b0;
        uint32_t aBl = aBh + 16384;

        float acc[2][8][4];
        #pragma unroll
        for (int mt = 0; mt < 2; ++mt)
            #pragma unroll
            for (int f = 0; f < 8; ++f)
                #pragma unroll
                for (int i = 0; i < 4; ++i) acc[mt][f][i] = 0.f;

        #pragma unroll
        for (int ks = 0; ks < 4; ++ks) {
            int p = ks * 2;
            uint32_t ah0[4], ah1[4], al0[4], al1[4];
            ldsm4(aAh + lmoff(p, wm * 32,      lane, 2048), ah0);
            ldsm4(aAh + lmoff(p, wm * 32 + 16, lane, 2048), ah1);
            ldsm4(aAl + lmoff(p, wm * 32,      lane, 2048), al0);
            ldsm4(aAl + lmoff(p, wm * 32 + 16, lane, 2048), al1);
            uint32_t bh[16], bl[16];
            #pragma unroll
            for (int s = 0; s < 4; ++s) {
                ldsm4(aBh + lmoff(p, wn * 64 + s * 16, lane, 2048), bh + 4 * s);
                ldsm4(aBl + lmoff(p, wn * 64 + s * 16, lane, 2048), bl + 4 * s);
            }
            #pragma unroll
            for (int f = 0; f < 8; ++f) {
                int q = (f >> 1) * 4 + (f & 1);
                uint32_t bfh[2] = { bh[q], bh[q + 2] };
                uint32_t bfl[2] = { bl[q], bl[q + 2] };
                mma16816(acc[0][f], ah0, bfh);
                mma16816(acc[0][f], ah0, bfl);
                mma16816(acc[0][f], al0, bfh);
                mma16816(acc[1][f], ah1, bfh);
                mma16816(acc[1][f], ah1, bfl);
                mma16816(acc[1][f], al1, bfh);
            }
        }

        // epilogue for this n-tile: y = acc + D*u
        int n0 = nt * 128;
        #pragma unroll
        for (int f = 0; f < 8; ++f) {
            int col = n0 + wn * 64 + f * 8 + 2 * tig;
            float2 dv = *(const float2*)(Dv + col);
            #pragma unroll
            for (int mt = 0; mt < 2; ++mt) {
                int r0 = m0 + wm * 32 + mt * 16 + g;
                float* a = acc[mt][f];
                size_t o0 = (size_t)r0 * DMODEL + col;
                size_t o1 = o0 + (size_t)8 * DMODEL;
                float2 u0 = *(const float2*)(u + o0);
                float2 u1 = *(const float2*)(u + o1);
                *(float2*)(y + o0) = make_float2(a[0] + dv.x * u0.x,
                                                 a[1] + dv.y * u0.y);
                *(float2*)(y + o1) = make_float2(a[2] + dv.x * u1.x,
                                                 a[3] + dv.y * u1.y);
            }
        }
        __syncthreads();
    }
    #undef G2_LDGB
    #undef G2_STSB
}

// ---------------- launch ----------------
extern "C" void kernel_launch(void* const* d_in, const int* in_sizes, int n_in,
                              void* d_out, int out_size) {
    const float* u    = (const float*)d_in[0];
    const float* Lur  = (const float*)d_in[1];
    const float* Lim  = (const float*)d_in[2];
    const float* Bre  = (const float*)d_in[3];
    const float* Bim  = (const float*)d_in[4];
    const float* Cre  = (const float*)d_in[5];
    const float* Cim  = (const float*)d_in[6];
    const float* Dv   = (const float*)d_in[7];
    const float* logD = (const float*)d_in[8];
    float* y = (float*)d_out;

    const int g1_bytes = 2 * G1_STAGE;   // 98304
    const int g2_bytes = 98304;
    cudaFuncSetAttribute(k_gemm1, cudaFuncAttributeMaxDynamicSharedMemorySize,
                         g1_bytes);
    cudaFuncSetAttribute(k_gemm2, cudaFuncAttributeMaxDynamicSharedMemorySize,
                         g2_bytes);

    k_params<<<1, 32>>>(Lur, Lim, logD);
    k_w1<<<128, 256>>>(Bre, Bim);
    k_w2<<<128, 256>>>(Cre, Cim);
    k_gemm1<<<MTOT / 128, 256, g1_bytes>>>(u);
    k_scan_local<<<(BATCH * NCHUNK) / 4, 128>>>();
    k_scan_prefix<<<1, BATCH * 32>>>();
    k_scan_fix<<<(BATCH * NCHUNK) / 4, 128>>>();
    k_gemm2<<<MTOT / 128, 256, g2_bytes>>>(u, Dv, y);
}

// round 10
// speedup vs baseline: 1.1390x; 1.1390x over previous
#include <cuda_runtime.h>
#include <cuda_bf16.h>
#include <cstdint>

#define BATCH   4
#define SEQL    4096
#define DMODEL  2048
#define HALF    32
#define N2      64
#define MTOT    (BATCH*SEQL)
#define SCHUNK  128              // scan chunk length (32 warps per batch)

// ---------------- scratch ----------------
__device__ __nv_bfloat16 g_W1h[N2 * DMODEL];   // [j][d]  B operand of GEMM1
__device__ __nv_bfloat16 g_W1l[N2 * DMODEL];
__device__ __nv_bfloat16 g_W2h[DMODEL * N2];   // [d][j]  B operand of GEMM2
__device__ __nv_bfloat16 g_W2l[DMODEL * N2];
__device__ float g_Bu[MTOT * N2];
__device__ __nv_bfloat16 g_Xh[MTOT * N2];      // corrected X, bf16 hi
__device__ __nv_bfloat16 g_Xl[MTOT * N2];      // corrected X, bf16 lo

// ---------------- helpers ----------------
__device__ __forceinline__ uint32_t smem_u32(const void* p) {
    uint32_t a;
    asm("{ .reg .u64 t; cvta.to.shared.u64 t, %1; cvt.u32.u64 %0, t; }"
        : "=r"(a) : "l"(p));
    return a;
}

__device__ __forceinline__ void cvt_hl(float x, uint16_t& h, uint16_t& l) {
    __nv_bfloat16 hb = __float2bfloat16_rn(x);
    float r = x - __bfloat162float(hb);
    __nv_bfloat16 lb = __float2bfloat16_rn(r);
    h = *(uint16_t*)&hb;
    l = *(uint16_t*)&lb;
}

// paired split: 2 floats -> packed bf16x2 hi + packed bf16x2 lo
__device__ __forceinline__ void cvt_hl2(float x0, float x1,
                                        uint32_t& h, uint32_t& l) {
    uint32_t hp;
    asm("cvt.rn.bf16x2.f32 %0, %1, %2;" : "=r"(hp) : "f"(x1), "f"(x0));
    float f0 = __uint_as_float(hp << 16);
    float f1 = __uint_as_float(hp & 0xffff0000u);
    float r0 = x0 - f0;
    float r1 = x1 - f1;
    asm("cvt.rn.bf16x2.f32 %0, %1, %2;" : "=r"(l) : "f"(r1), "f"(r0));
    h = hp;
}

__device__ __forceinline__ void cvt8(const float4& v0, const float4& v1,
                                     uint4& h, uint4& l) {
    cvt_hl2(v0.x, v0.y, h.x, l.x);
    cvt_hl2(v0.z, v0.w, h.y, l.y);
    cvt_hl2(v1.x, v1.y, h.z, l.z);
    cvt_hl2(v1.z, v1.w, h.w, l.w);
}

__device__ __forceinline__ void mma16816(float* c, const uint32_t* a,
                                         const uint32_t* b) {
    asm volatile(
        "mma.sync.aligned.m16n8k16.row.col.f32.bf16.bf16.f32 "
        "{%0,%1,%2,%3}, {%4,%5,%6,%7}, {%8,%9}, {%0,%1,%2,%3};"
        : "+f"(c[0]), "+f"(c[1]), "+f"(c[2]), "+f"(c[3])
        : "r"(a[0]), "r"(a[1]), "r"(a[2]), "r"(a[3]), "r"(b[0]), "r"(b[1]));
}

__device__ __forceinline__ void ldsm4(uint32_t addr, uint32_t* r) {
    asm volatile(
        "ldmatrix.sync.aligned.m8n8.x4.shared.b16 {%0,%1,%2,%3}, [%4];"
        : "=r"(r[0]), "=r"(r[1]), "=r"(r[2]), "=r"(r[3]) : "r"(addr));
}

// Panels: kp holds 8 k-values; 16B per row; XOR(row, kp) swizzle.
__device__ __forceinline__ uint32_t lmoff(int p, int rb, int lane, int psz) {
    int pp = p + (lane >> 4);
    int row = rb + (lane & 15);
    return (uint32_t)(pp * psz + (((row ^ (pp & 7)) << 4)));
}

// per-state discrete params (thread n < 32)
__device__ __forceinline__ void state_params(const float* Lur, const float* Lim,
                                             const float* logD, int n,
                                             float& lbr, float& lbi,
                                             float& sre, float& sim) {
    float x   = Lur[n];
    float sp  = (x > 20.f) ? x : log1pf(expf(x));
    float lre = -(sp + 1e-4f + 0.01f);
    float lim = Lim[n];
    float dt  = expf(logD[n]);
    float ar = lre * dt, ai = lim * dt;
    float er = expf(ar);
    lbr = er * cosf(ai);
    lbi = er * sinf(ai);
    float den = lre * lre + lim * lim;
    float nr = lbr - 1.f, ni = lbi;
    sre = (nr * lre + ni * lim) / den;
    sim = (ni * lre - nr * lim) / den;
}

// ---------------- fused weight prep (params computed per block) ----------------
__global__ void k_wprep(const float* __restrict__ Lur,
                        const float* __restrict__ Lim,
                        const float* __restrict__ logD,
                        const float* __restrict__ Bre,
                        const float* __restrict__ Bim,
                        const float* __restrict__ Cre,
                        const float* __restrict__ Cim) {
    __shared__ float s_sre[HALF], s_sim[HALF];
    if (threadIdx.x < HALF) {
        float lbr, lbi, sre, sim;
        state_params(Lur, Lim, logD, threadIdx.x, lbr, lbi, sre, sim);
        s_sre[threadIdx.x] = sre;
        s_sim[threadIdx.x] = sim;
    }
    __syncthreads();
    const int total = N2 * DMODEL;
    for (int idx = blockIdx.x * blockDim.x + threadIdx.x; idx < total;
         idx += gridDim.x * blockDim.x) {
        // W1 [j][d]
        {
            int j = idx >> 11;
            int d = idx & 2047;
            int n = j & 31;
            float br = Bre[n * DMODEL + d], bi = Bim[n * DMODEL + d];
            float v = (j < 32) ? (s_sre[n] * br - s_sim[n] * bi)
                               : (s_sre[n] * bi + s_sim[n] * br);
            uint16_t h, l;
            cvt_hl(v, h, l);
            g_W1h[idx] = *(__nv_bfloat16*)&h;
            g_W1l[idx] = *(__nv_bfloat16*)&l;
        }
        // W2 [d][j]
        {
            int d = idx >> 6;
            int j = idx & 63;
            float v = (j < 32) ? (2.f * Cre[d * HALF + j])
                               : (-2.f * Cim[d * HALF + (j - 32)]);
            uint16_t h, l;
            cvt_hl(v, h, l);
            g_W2h[idx] = *(__nv_bfloat16*)&h;
            g_W2l[idx] = *(__nv_bfloat16*)&l;
        }
    }
}

// ---------------- GEMM1: Bu = u @ W1^T  (bf16x3 HMMA, LDSM, 2-stage) --------
// (round-8 proven version) 256 thr, BM=128, BN=64, K_TILE=64, grid 128.
#define G1_STAGE 49152
__global__ __launch_bounds__(256) void k_gemm1(const float* __restrict__ u) {
    extern __shared__ char smem[];
    int tid = threadIdx.x;
    int lane = tid & 31, g = lane >> 2, tig = lane & 3;
    int w = tid >> 5, wm = w >> 1, wn = w & 1;
    int m0 = blockIdx.x * 128;

    float acc[2][4][4];
    #pragma unroll
    for (int mt = 0; mt < 2; ++mt)
        #pragma unroll
        for (int f = 0; f < 4; ++f)
            #pragma unroll
            for (int i = 0; i < 4; ++i) acc[mt][f][i] = 0.f;

    uint32_t oAh0[4], oAh1[4], oAl0[4], oAl1[4];
    uint32_t oBh0[4], oBh1[4], oBl0[4], oBl1[4];
    #pragma unroll
    for (int ks = 0; ks < 4; ++ks) {
        int p = ks * 2;
        oAh0[ks] =         lmoff(p, wm * 32,      lane, 2048);
        oAh1[ks] =         lmoff(p, wm * 32 + 16, lane, 2048);
        oAl0[ks] = 16384 + lmoff(p, wm * 32,      lane, 2048);
        oAl1[ks] = 16384 + lmoff(p, wm * 32 + 16, lane, 2048);
        oBh0[ks] = 32768 + lmoff(p, wn * 32,      lane, 1024);
        oBh1[ks] = 32768 + lmoff(p, wn * 32 + 16, lane, 1024);
        oBl0[ks] = 40960 + lmoff(p, wn * 32,      lane, 1024);
        oBl1[ks] = 40960 + lmoff(p, wn * 32 + 16, lane, 1024);
    }
    uint32_t sb0 = smem_u32(smem);
    uint32_t sb1 = sb0 + G1_STAGE;

    float4 ru[4][2];
    uint4 rwh[2], rwl[2];

    #define G1_LDG(kb)                                                        \
        _Pragma("unroll")                                                     \
        for (int i = 0; i < 4; ++i) {                                         \
            int task = tid + 256 * i;                                         \
            int row = task >> 3, kp = task & 7;                               \
            const float* s = u + (size_t)(m0 + row) * DMODEL + (kb) + kp * 8; \
            ru[i][0] = *(const float4*)s;                                     \
            ru[i][1] = *(const float4*)(s + 4);                               \
        }                                                                     \
        _Pragma("unroll")                                                     \
        for (int i = 0; i < 2; ++i) {                                         \
            int task = tid + 256 * i;                                         \
            int n = task >> 3, kp = task & 7;                                 \
            size_t off = ((size_t)n * DMODEL + (kb) + kp * 8) * 2;            \
            rwh[i] = *(const uint4*)((const char*)g_W1h + off);               \
            rwl[i] = *(const uint4*)((const char*)g_W1l + off);               \
        }

    #define G1_STS(sbase)                                                     \
        _Pragma("unroll")                                                     \
        for (int i = 0; i < 4; ++i) {                                         \
            int task = tid + 256 * i;                                         \
            int row = task >> 3, kp = task & 7;                               \
            uint4 h, l;                                                       \
            cvt8(ru[i][0], ru[i][1], h, l);                                   \
            int off = kp * 2048 + ((row ^ kp) << 4);                          \
            *(uint4*)((sbase) + off) = h;                                     \
            *(uint4*)((sbase) + 16384 + off) = l;                             \
        }                                                                     \
        _Pragma("unroll")                                                     \
        for (int i = 0; i < 2; ++i) {                                         \
            int task = tid + 256 * i;                                         \
            int n = task >> 3, kp = task & 7;                                 \
            int off = kp * 1024 + ((n ^ kp) << 4);                            \
            *(uint4*)((sbase) + 32768 + off) = rwh[i];                        \
            *(uint4*)((sbase) + 40960 + off) = rwl[i];                        \
        }

    G1_LDG(0);
    G1_STS(smem);
    G1_LDG(64);
    __syncthreads();

    for (int kt = 0; kt < DMODEL / 64; ++kt) {
        if (kt + 1 < DMODEL / 64) {
            char* nst = smem + ((kt + 1) & 1) * G1_STAGE;
            G1_STS(nst);
        }
        if (kt + 2 < DMODEL / 64) {
            G1_LDG((kt + 2) * 64);
        }
        uint32_t sb = (kt & 1) ? sb1 : sb0;
        #pragma unroll
        for (int ks = 0; ks < 4; ++ks) {
            uint32_t ah0[4], ah1[4], al0[4], al1[4];
            ldsm4(sb + oAh0[ks], ah0);
            ldsm4(sb + oAh1[ks], ah1);
            ldsm4(sb + oAl0[ks], al0);
            ldsm4(sb + oAl1[ks], al1);
            uint32_t bh[8], bl[8];
            ldsm4(sb + oBh0[ks], bh);
            ldsm4(sb + oBh1[ks], bh + 4);
            ldsm4(sb + oBl0[ks], bl);
            ldsm4(sb + oBl1[ks], bl + 4);
            #pragma unroll
            for (int f = 0; f < 4; ++f) {
                int q = (f >> 1) * 4 + (f & 1);
                uint32_t bfh[2] = { bh[q], bh[q + 2] };
                uint32_t bfl[2] = { bl[q], bl[q + 2] };
                mma16816(acc[0][f], ah0, bfh);
                mma16816(acc[0][f], ah0, bfl);
                mma16816(acc[0][f], al0, bfh);
                mma16816(acc[1][f], ah1, bfh);
                mma16816(acc[1][f], ah1, bfl);
                mma16816(acc[1][f], al1, bfh);
            }
        }
        __syncthreads();
    }
    #pragma unroll
    for (int mt = 0; mt < 2; ++mt) {
        int r0 = m0 + wm * 32 + mt * 16 + g;
        #pragma unroll
        for (int f = 0; f < 4; ++f) {
            int col = wn * 32 + f * 8 + 2 * tig;
            float* a = acc[mt][f];
            *(float2*)(g_Bu + (size_t)r0 * N2 + col)       = make_float2(a[0], a[1]);
            *(float2*)(g_Bu + (size_t)(r0 + 8) * N2 + col) = make_float2(a[2], a[3]);
        }
    }
    #undef G1_LDG
    #undef G1_STS
}

// ---------------- fused scan: 4 blocks (one per batch), 1024 thr ----------------
// Warp w handles chunk w (length 128). Phase1: carry only (no intermediate
// writes). Phase2: warp 0 serial prefix with lbar^128. Phase3: re-scan with
// fixup, emit bf16 hi/lo X.
__global__ __launch_bounds__(1024) void k_scan(const float* __restrict__ Lur,
                                               const float* __restrict__ Lim,
                                               const float* __restrict__ logD) {
    __shared__ float s_lbr[32], s_lbi[32], s_lbSr[32], s_lbSi[32];
    __shared__ float s_car[32 * N2];    // chunk carries
    __shared__ float s_pre[32 * N2];    // exclusive prefixes
    int tid = threadIdx.x;
    int w = tid >> 5, lane = tid & 31;
    int b = blockIdx.x;

    if (tid < 32) {
        float x   = Lur[tid];
        float sp  = (x > 20.f) ? x : log1pf(expf(x));
        float lre = -(sp + 1e-4f + 0.01f);
        float lim = Lim[tid];
        float dt  = expf(logD[tid]);
        float ar = lre * dt, ai = lim * dt;
        float er = expf(ar);
        s_lbr[tid] = er * cosf(ai);
        s_lbi[tid] = er * sinf(ai);
        float erS = expf((float)SCHUNK * ar);
        float aS  = (float)SCHUNK * ai;
        s_lbSr[tid] = erS * cosf(aS);
        s_lbSi[tid] = erS * sinf(aS);
    }
    __syncthreads();

    float lbr = s_lbr[lane], lbi = s_lbi[lane];
    size_t base = ((size_t)b * SEQL + (size_t)w * SCHUNK) * N2;

    // phase 1: local scan, carry only
    {
        float xr = 0.f, xi = 0.f;
        for (int i = 0; i < SCHUNK; ++i) {
            size_t off = base + (size_t)i * N2;
            float br = g_Bu[off + lane];
            float bi = g_Bu[off + 32 + lane];
            float nr = fmaf(lbr, xr, fmaf(-lbi, xi, br));
            float ni = fmaf(lbr, xi, fmaf( lbi, xr, bi));
            xr = nr; xi = ni;
        }
        s_car[w * N2 + lane]      = xr;
        s_car[w * N2 + 32 + lane] = xi;
    }
    __syncthreads();

    // phase 2: serial prefix over 32 chunk carries (warp 0)
    if (w == 0) {
        float lbSr = s_lbSr[lane], lbSi = s_lbSi[lane];
        float Pr = 0.f, Pi = 0.f;
        for (int c = 0; c < 32; ++c) {
            s_pre[c * N2 + lane]      = Pr;
            s_pre[c * N2 + 32 + lane] = Pi;
            float cr = s_car[c * N2 + lane];
            float ci = s_car[c * N2 + 32 + lane];
            float nr = fmaf(lbSr, Pr, fmaf(-lbSi, Pi, cr));
            float ni = fmaf(lbSr, Pi, fmaf( lbSi, Pr, ci));
            Pr = nr; Pi = ni;
        }
    }
    __syncthreads();

    // phase 3: re-scan + fixup, emit bf16 hi/lo
    {
        float Pr = s_pre[w * N2 + lane], Pi = s_pre[w * N2 + 32 + lane];
        float pr = lbr, pi = lbi;         // lbar^(i+1)
        float xr = 0.f, xi = 0.f;         // local scan
        for (int i = 0; i < SCHUNK; ++i) {
            size_t off = base + (size_t)i * N2;
            float br = g_Bu[off + lane];
            float bi = g_Bu[off + 32 + lane];
            float nr = fmaf(lbr, xr, fmaf(-lbi, xi, br));
            float ni = fmaf(lbr, xi, fmaf( lbi, xr, bi));
            xr = nr; xi = ni;
            float fxr = fmaf(pr, Pr, fmaf(-pi, Pi, xr));
            float fxi = fmaf(pr, Pi, fmaf( pi, Pr, xi));
            uint16_t hr, lr, hi_, li_;
            cvt_hl(fxr, hr, lr);
            cvt_hl(fxi, hi_, li_);
            g_Xh[off + lane]      = *(__nv_bfloat16*)&hr;
            g_Xh[off + 32 + lane] = *(__nv_bfloat16*)&hi_;
            g_Xl[off + lane]      = *(__nv_bfloat16*)&lr;
            g_Xl[off + 32 + lane] = *(__nv_bfloat16*)&li_;
            float npr = pr * lbr - pi * lbi;
            float npi = pr * lbi + pi * lbr;
            pr = npr; pi = npi;
        }
    }
}

// ---------------- GEMM2: y = X @ W2 + D.u  (round-8 proven version) ----------
// 256 thr, BM=128, BN=128, K=64 single tile; grid (16, 128); warp = m32 x n64.
__global__ __launch_bounds__(256) void k_gemm2(const float* __restrict__ u,
                                               const float* __restrict__ Dv,
                                               float* __restrict__ y) {
    extern __shared__ char smem[];
    char* pAh = smem;
    char* pAl = smem + 16384;
    char* pBh = smem + 32768;
    char* pBl = smem + 49152;
    int tid = threadIdx.x;
    int lane = tid & 31, g = lane >> 2, tig = lane & 3;
    int w = tid >> 5, wm = w >> 1, wn = w & 1;
    int n0 = blockIdx.x * 128;
    int m0 = blockIdx.y * 128;

    #pragma unroll
    for (int i = 0; i < 4; ++i) {
        int task = tid + 256 * i;
        int row = task >> 3, kp = task & 7;
        size_t goff = ((size_t)(m0 + row) * N2 + kp * 8) * 2;
        int off = kp * 2048 + ((row ^ kp) << 4);
        *(uint4*)(pAh + off) = *(const uint4*)((const char*)g_Xh + goff);
        *(uint4*)(pAl + off) = *(const uint4*)((const char*)g_Xl + goff);
    }
    #pragma unroll
    for (int i = 0; i < 4; ++i) {
        int task = tid + 256 * i;
        int n = task >> 3, kp = task & 7;
        size_t goff = ((size_t)(n0 + n) * N2 + kp * 8) * 2;
        int off = kp * 2048 + ((n ^ kp) << 4);
        *(uint4*)(pBh + off) = *(const uint4*)((const char*)g_W2h + goff);
        *(uint4*)(pBl + off) = *(const uint4*)((const char*)g_W2l + goff);
    }
    __syncthreads();

    float acc[2][8][4];
    #pragma unroll
    for (int mt = 0; mt < 2; ++mt)
        #pragma unroll
        for (int f = 0; f < 8; ++f)
            #pragma unroll
            for (int i = 0; i < 4; ++i) acc[mt][f][i] = 0.f;

    uint32_t aBh = smem_u32(pBh), aBl = smem_u32(pBl);
    uint32_t aAh = smem_u32(pAh), aAl = smem_u32(pAl);

    #pragma unroll
    for (int ks = 0; ks < 4; ++ks) {
        int p = ks * 2;
        uint32_t ah0[4], ah1[4], al0[4], al1[4];
        ldsm4(aAh + lmoff(p, wm * 32,      lane, 2048), ah0);
        ldsm4(aAh + lmoff(p, wm * 32 + 16, lane, 2048), ah1);
        ldsm4(aAl + lmoff(p, wm * 32,      lane, 2048), al0);
        ldsm4(aAl + lmoff(p, wm * 32 + 16, lane, 2048), al1);
        uint32_t bh[16], bl[16];
        #pragma unroll
        for (int s = 0; s < 4; ++s) {
            ldsm4(aBh + lmoff(p, wn * 64 + s * 16, lane, 2048), bh + 4 * s);
            ldsm4(aBl + lmoff(p, wn * 64 + s * 16, lane, 2048), bl + 4 * s);
        }
        #pragma unroll
        for (int f = 0; f < 8; ++f) {
            int q = (f >> 1) * 4 + (f & 1);
            uint32_t bfh[2] = { bh[q], bh[q + 2] };
            uint32_t bfl[2] = { bl[q], bl[q + 2] };
            mma16816(acc[0][f], ah0, bfh);
            mma16816(acc[0][f], ah0, bfl);
            mma16816(acc[0][f], al0, bfh);
            mma16816(acc[1][f], ah1, bfh);
            mma16816(acc[1][f], ah1, bfl);
            mma16816(acc[1][f], al1, bfh);
        }
    }

    #pragma unroll
    for (int f = 0; f < 8; ++f) {
        int col = n0 + wn * 64 + f * 8 + 2 * tig;
        float2 dv = *(const float2*)(Dv + col);
        #pragma unroll
        for (int mt = 0; mt < 2; ++mt) {
            int r0 = m0 + wm * 32 + mt * 16 + g;
            float* a = acc[mt][f];
            size_t o0 = (size_t)r0 * DMODEL + col;
            size_t o1 = o0 + (size_t)8 * DMODEL;
            float2 u0 = *(const float2*)(u + o0);
            float2 u1 = *(const float2*)(u + o1);
            *(float2*)(y + o0) = make_float2(a[0] + dv.x * u0.x, a[1] + dv.y * u0.y);
            *(float2*)(y + o1) = make_float2(a[2] + dv.x * u1.x, a[3] + dv.y * u1.y);
        }
    }
}

// ---------------- launch ----------------
extern "C" void kernel_launch(void* const* d_in, const int* in_sizes, int n_in,
                              void* d_out, int out_size) {
    const float* u    = (const float*)d_in[0];
    const float* Lur  = (const float*)d_in[1];
    const float* Lim  = (const float*)d_in[2];
    const float* Bre  = (const float*)d_in[3];
    const float* Bim  = (const float*)d_in[4];
    const float* Cre  = (const float*)d_in[5];
    const float* Cim  = (const float*)d_in[6];
    const float* Dv   = (const float*)d_in[7];
    const float* logD = (const float*)d_in[8];
    float* y = (float*)d_out;

    const int g1_bytes = 2 * G1_STAGE;   // 98304
    const int g2_bytes = 65536;
    cudaFuncSetAttribute(k_gemm1, cudaFuncAttributeMaxDynamicSharedMemorySize,
                         g1_bytes);
    cudaFuncSetAttribute(k_gemm2, cudaFuncAttributeMaxDynamicSharedMemorySize,
                         g2_bytes);

    k_wprep<<<128, 256>>>(Lur, Lim, logD, Bre, Bim, Cre, Cim);
    k_gemm1<<<MTOT / 128, 256, g1_bytes>>>(u);
    k_scan<<<BATCH, 1024>>>(Lur, Lim, logD);
    k_gemm2<<<dim3(DMODEL / 128, MTOT / 128), 256, g2_bytes>>>(u, Dv, y);
}

// round 11
// speedup vs baseline: 1.2091x; 1.0615x over previous
#include <cuda_runtime.h>
#include <cuda_bf16.h>
#include <cstdint>

#define BATCH   4
#define SEQL    4096
#define DMODEL  2048
#define HALF    32
#define N2      64
#define MTOT    (BATCH*SEQL)
#define SCHUNK  128              // scan chunk length (32 warps per batch)

// ---------------- scratch ----------------
__device__ __nv_bfloat16 g_W1h[N2 * DMODEL];   // [j][d]  B operand of GEMM1
__device__ __nv_bfloat16 g_W1l[N2 * DMODEL];
__device__ __nv_bfloat16 g_W2h[DMODEL * N2];   // [d][j]  B operand of GEMM2
__device__ __nv_bfloat16 g_W2l[DMODEL * N2];
__device__ float g_Bu[MTOT * N2];
__device__ __nv_bfloat16 g_Xh[MTOT * N2];      // corrected X, bf16 hi
__device__ __nv_bfloat16 g_Xl[MTOT * N2];      // corrected X, bf16 lo

// ---------------- helpers ----------------
__device__ __forceinline__ uint32_t smem_u32(const void* p) {
    uint32_t a;
    asm("{ .reg .u64 t; cvta.to.shared.u64 t, %1; cvt.u32.u64 %0, t; }"
        : "=r"(a) : "l"(p));
    return a;
}

__device__ __forceinline__ void cvt_hl(float x, uint16_t& h, uint16_t& l) {
    __nv_bfloat16 hb = __float2bfloat16_rn(x);
    float r = x - __bfloat162float(hb);
    __nv_bfloat16 lb = __float2bfloat16_rn(r);
    h = *(uint16_t*)&hb;
    l = *(uint16_t*)&lb;
}

// paired split: 2 floats -> packed bf16x2 hi + packed bf16x2 lo
__device__ __forceinline__ void cvt_hl2(float x0, float x1,
                                        uint32_t& h, uint32_t& l) {
    uint32_t hp;
    asm("cvt.rn.bf16x2.f32 %0, %1, %2;" : "=r"(hp) : "f"(x1), "f"(x0));
    float f0 = __uint_as_float(hp << 16);
    float f1 = __uint_as_float(hp & 0xffff0000u);
    float r0 = x0 - f0;
    float r1 = x1 - f1;
    asm("cvt.rn.bf16x2.f32 %0, %1, %2;" : "=r"(l) : "f"(r1), "f"(r0));
    h = hp;
}

__device__ __forceinline__ void cvt8(const float4& v0, const float4& v1,
                                     uint4& h, uint4& l) {
    cvt_hl2(v0.x, v0.y, h.x, l.x);
    cvt_hl2(v0.z, v0.w, h.y, l.y);
    cvt_hl2(v1.x, v1.y, h.z, l.z);
    cvt_hl2(v1.z, v1.w, h.w, l.w);
}

__device__ __forceinline__ void mma16816(float* c, const uint32_t* a,
                                         const uint32_t* b) {
    asm volatile(
        "mma.sync.aligned.m16n8k16.row.col.f32.bf16.bf16.f32 "
        "{%0,%1,%2,%3}, {%4,%5,%6,%7}, {%8,%9}, {%0,%1,%2,%3};"
        : "+f"(c[0]), "+f"(c[1]), "+f"(c[2]), "+f"(c[3])
        : "r"(a[0]), "r"(a[1]), "r"(a[2]), "r"(a[3]), "r"(b[0]), "r"(b[1]));
}

__device__ __forceinline__ void ldsm4(uint32_t addr, uint32_t* r) {
    asm volatile(
        "ldmatrix.sync.aligned.m8n8.x4.shared.b16 {%0,%1,%2,%3}, [%4];"
        : "=r"(r[0]), "=r"(r[1]), "=r"(r[2]), "=r"(r[3]) : "r"(addr));
}

// Panels: kp holds 8 k-values; 16B per row; XOR(row, kp) swizzle.
__device__ __forceinline__ uint32_t lmoff(int p, int rb, int lane, int psz) {
    int pp = p + (lane >> 4);
    int row = rb + (lane & 15);
    return (uint32_t)(pp * psz + (((row ^ (pp & 7)) << 4)));
}

// per-state discrete params (thread n < 32)
__device__ __forceinline__ void state_params(const float* Lur, const float* Lim,
                                             const float* logD, int n,
                                             float& lbr, float& lbi,
                                             float& sre, float& sim) {
    float x   = Lur[n];
    float sp  = (x > 20.f) ? x : log1pf(expf(x));
    float lre = -(sp + 1e-4f + 0.01f);
    float lim = Lim[n];
    float dt  = expf(logD[n]);
    float ar = lre * dt, ai = lim * dt;
    float er = expf(ar);
    lbr = er * cosf(ai);
    lbi = er * sinf(ai);
    float den = lre * lre + lim * lim;
    float nr = lbr - 1.f, ni = lbi;
    sre = (nr * lre + ni * lim) / den;
    sim = (ni * lre - nr * lim) / den;
}

// ---------------- fused weight prep ----------------
__global__ void k_wprep(const float* __restrict__ Lur,
                        const float* __restrict__ Lim,
                        const float* __restrict__ logD,
                        const float* __restrict__ Bre,
                        const float* __restrict__ Bim,
                        const float* __restrict__ Cre,
                        const float* __restrict__ Cim) {
    __shared__ float s_sre[HALF], s_sim[HALF];
    if (threadIdx.x < HALF) {
        float lbr, lbi, sre, sim;
        state_params(Lur, Lim, logD, threadIdx.x, lbr, lbi, sre, sim);
        s_sre[threadIdx.x] = sre;
        s_sim[threadIdx.x] = sim;
    }
    __syncthreads();
    const int total = N2 * DMODEL;
    for (int idx = blockIdx.x * blockDim.x + threadIdx.x; idx < total;
         idx += gridDim.x * blockDim.x) {
        {
            int j = idx >> 11;
            int d = idx & 2047;
            int n = j & 31;
            float br = Bre[n * DMODEL + d], bi = Bim[n * DMODEL + d];
            float v = (j < 32) ? (s_sre[n] * br - s_sim[n] * bi)
                               : (s_sre[n] * bi + s_sim[n] * br);
            uint16_t h, l;
            cvt_hl(v, h, l);
            g_W1h[idx] = *(__nv_bfloat16*)&h;
            g_W1l[idx] = *(__nv_bfloat16*)&l;
        }
        {
            int d = idx >> 6;
            int j = idx & 63;
            float v = (j < 32) ? (2.f * Cre[d * HALF + j])
                               : (-2.f * Cim[d * HALF + (j - 32)]);
            uint16_t h, l;
            cvt_hl(v, h, l);
            g_W2h[idx] = *(__nv_bfloat16*)&h;
            g_W2l[idx] = *(__nv_bfloat16*)&l;
        }
    }
}

// ---------------- GEMM1 (round-8 proven) ----------------
#define G1_STAGE 49152
__global__ __launch_bounds__(256) void k_gemm1(const float* __restrict__ u) {
    extern __shared__ char smem[];
    int tid = threadIdx.x;
    int lane = tid & 31, g = lane >> 2, tig = lane & 3;
    int w = tid >> 5, wm = w >> 1, wn = w & 1;
    int m0 = blockIdx.x * 128;

    float acc[2][4][4];
    #pragma unroll
    for (int mt = 0; mt < 2; ++mt)
        #pragma unroll
        for (int f = 0; f < 4; ++f)
            #pragma unroll
            for (int i = 0; i < 4; ++i) acc[mt][f][i] = 0.f;

    uint32_t oAh0[4], oAh1[4], oAl0[4], oAl1[4];
    uint32_t oBh0[4], oBh1[4], oBl0[4], oBl1[4];
    #pragma unroll
    for (int ks = 0; ks < 4; ++ks) {
        int p = ks * 2;
        oAh0[ks] =         lmoff(p, wm * 32,      lane, 2048);
        oAh1[ks] =         lmoff(p, wm * 32 + 16, lane, 2048);
        oAl0[ks] = 16384 + lmoff(p, wm * 32,      lane, 2048);
        oAl1[ks] = 16384 + lmoff(p, wm * 32 + 16, lane, 2048);
        oBh0[ks] = 32768 + lmoff(p, wn * 32,      lane, 1024);
        oBh1[ks] = 32768 + lmoff(p, wn * 32 + 16, lane, 1024);
        oBl0[ks] = 40960 + lmoff(p, wn * 32,      lane, 1024);
        oBl1[ks] = 40960 + lmoff(p, wn * 32 + 16, lane, 1024);
    }
    uint32_t sb0 = smem_u32(smem);
    uint32_t sb1 = sb0 + G1_STAGE;

    float4 ru[4][2];
    uint4 rwh[2], rwl[2];

    #define G1_LDG(kb)                                                        \
        _Pragma("unroll")                                                     \
        for (int i = 0; i < 4; ++i) {                                         \
            int task = tid + 256 * i;                                         \
            int row = task >> 3, kp = task & 7;                               \
            const float* s = u + (size_t)(m0 + row) * DMODEL + (kb) + kp * 8; \
            ru[i][0] = *(const float4*)s;                                     \
            ru[i][1] = *(const float4*)(s + 4);                               \
        }                                                                     \
        _Pragma("unroll")                                                     \
        for (int i = 0; i < 2; ++i) {                                         \
            int task = tid + 256 * i;                                         \
            int n = task >> 3, kp = task & 7;                                 \
            size_t off = ((size_t)n * DMODEL + (kb) + kp * 8) * 2;            \
            rwh[i] = *(const uint4*)((const char*)g_W1h + off);               \
            rwl[i] = *(const uint4*)((const char*)g_W1l + off);               \
        }

    #define G1_STS(sbase)                                                     \
        _Pragma("unroll")                                                     \
        for (int i = 0; i < 4; ++i) {                                         \
            int task = tid + 256 * i;                                         \
            int row = task >> 3, kp = task & 7;                               \
            uint4 h, l;                                                       \
            cvt8(ru[i][0], ru[i][1], h, l);                                   \
            int off = kp * 2048 + ((row ^ kp) << 4);                          \
            *(uint4*)((sbase) + off) = h;                                     \
            *(uint4*)((sbase) + 16384 + off) = l;                             \
        }                                                                     \
        _Pragma("unroll")                                                     \
        for (int i = 0; i < 2; ++i) {                                         \
            int task = tid + 256 * i;                                         \
            int n = task >> 3, kp = task & 7;                                 \
            int off = kp * 1024 + ((n ^ kp) << 4);                            \
            *(uint4*)((sbase) + 32768 + off) = rwh[i];                        \
            *(uint4*)((sbase) + 40960 + off) = rwl[i];                        \
        }

    G1_LDG(0);
    G1_STS(smem);
    G1_LDG(64);
    __syncthreads();

    for (int kt = 0; kt < DMODEL / 64; ++kt) {
        if (kt + 1 < DMODEL / 64) {
            char* nst = smem + ((kt + 1) & 1) * G1_STAGE;
            G1_STS(nst);
        }
        if (kt + 2 < DMODEL / 64) {
            G1_LDG((kt + 2) * 64);
        }
        uint32_t sb = (kt & 1) ? sb1 : sb0;
        #pragma unroll
        for (int ks = 0; ks < 4; ++ks) {
            uint32_t ah0[4], ah1[4], al0[4], al1[4];
            ldsm4(sb + oAh0[ks], ah0);
            ldsm4(sb + oAh1[ks], ah1);
            ldsm4(sb + oAl0[ks], al0);
            ldsm4(sb + oAl1[ks], al1);
            uint32_t bh[8], bl[8];
            ldsm4(sb + oBh0[ks], bh);
            ldsm4(sb + oBh1[ks], bh + 4);
            ldsm4(sb + oBl0[ks], bl);
            ldsm4(sb + oBl1[ks], bl + 4);
            #pragma unroll
            for (int f = 0; f < 4; ++f) {
                int q = (f >> 1) * 4 + (f & 1);
                uint32_t bfh[2] = { bh[q], bh[q + 2] };
                uint32_t bfl[2] = { bl[q], bl[q + 2] };
                mma16816(acc[0][f], ah0, bfh);
                mma16816(acc[0][f], ah0, bfl);
                mma16816(acc[0][f], al0, bfh);
                mma16816(acc[1][f], ah1, bfh);
                mma16816(acc[1][f], ah1, bfl);
                mma16816(acc[1][f], al1, bfh);
            }
        }
        __syncthreads();
    }
    #pragma unroll
    for (int mt = 0; mt < 2; ++mt) {
        int r0 = m0 + wm * 32 + mt * 16 + g;
        #pragma unroll
        for (int f = 0; f < 4; ++f) {
            int col = wn * 32 + f * 8 + 2 * tig;
            float* a = acc[mt][f];
            *(float2*)(g_Bu + (size_t)r0 * N2 + col)       = make_float2(a[0], a[1]);
            *(float2*)(g_Bu + (size_t)(r0 + 8) * N2 + col) = make_float2(a[2], a[3]);
        }
    }
    #undef G1_LDG
    #undef G1_STS
}

// ---------------- fused scan: 4 blocks (one per batch), 1024 thr ----------------
__global__ __launch_bounds__(1024) void k_scan(const float* __restrict__ Lur,
                                               const float* __restrict__ Lim,
                                               const float* __restrict__ logD) {
    __shared__ float s_lbr[32], s_lbi[32], s_lbSr[32], s_lbSi[32];
    __shared__ float s_car[32 * N2];
    __shared__ float s_pre[32 * N2];
    int tid = threadIdx.x;
    int w = tid >> 5, lane = tid & 31;
    int b = blockIdx.x;

    if (tid < 32) {
        float x   = Lur[tid];
        float sp  = (x > 20.f) ? x : log1pf(expf(x));
        float lre = -(sp + 1e-4f + 0.01f);
        float lim = Lim[tid];
        float dt  = expf(logD[tid]);
        float ar = lre * dt, ai = lim * dt;
        float er = expf(ar);
        s_lbr[tid] = er * cosf(ai);
        s_lbi[tid] = er * sinf(ai);
        float erS = expf((float)SCHUNK * ar);
        float aS  = (float)SCHUNK * ai;
        s_lbSr[tid] = erS * cosf(aS);
        s_lbSi[tid] = erS * sinf(aS);
    }
    __syncthreads();

    float lbr = s_lbr[lane], lbi = s_lbi[lane];
    size_t base = ((size_t)b * SEQL + (size_t)w * SCHUNK) * N2;

    // phase 1: local scan, carry only
    {
        float xr = 0.f, xi = 0.f;
        for (int i = 0; i < SCHUNK; ++i) {
            size_t off = base + (size_t)i * N2;
            float br = g_Bu[off + lane];
            float bi = g_Bu[off + 32 + lane];
            float nr = fmaf(lbr, xr, fmaf(-lbi, xi, br));
            float ni = fmaf(lbr, xi, fmaf( lbi, xr, bi));
            xr = nr; xi = ni;
        }
        s_car[w * N2 + lane]      = xr;
        s_car[w * N2 + 32 + lane] = xi;
    }
    __syncthreads();

    // phase 2: serial prefix (warp 0)
    if (w == 0) {
        float lbSr = s_lbSr[lane], lbSi = s_lbSi[lane];
        float Pr = 0.f, Pi = 0.f;
        for (int c = 0; c < 32; ++c) {
            s_pre[c * N2 + lane]      = Pr;
            s_pre[c * N2 + 32 + lane] = Pi;
            float cr = s_car[c * N2 + lane];
            float ci = s_car[c * N2 + 32 + lane];
            float nr = fmaf(lbSr, Pr, fmaf(-lbSi, Pi, cr));
            float ni = fmaf(lbSr, Pi, fmaf( lbSi, Pr, ci));
            Pr = nr; Pi = ni;
        }
    }
    __syncthreads();

    // phase 3: re-scan + fixup, emit bf16 hi/lo
    {
        float Pr = s_pre[w * N2 + lane], Pi = s_pre[w * N2 + 32 + lane];
        float pr = lbr, pi = lbi;
        float xr = 0.f, xi = 0.f;
        for (int i = 0; i < SCHUNK; ++i) {
            size_t off = base + (size_t)i * N2;
            float br = g_Bu[off + lane];
            float bi = g_Bu[off + 32 + lane];
            float nr = fmaf(lbr, xr, fmaf(-lbi, xi, br));
            float ni = fmaf(lbr, xi, fmaf( lbi, xr, bi));
            xr = nr; xi = ni;
            float fxr = fmaf(pr, Pr, fmaf(-pi, Pi, xr));
            float fxi = fmaf(pr, Pi, fmaf( pi, Pr, xi));
            uint16_t hr, lr, hi_, li_;
            cvt_hl(fxr, hr, lr);
            cvt_hl(fxi, hi_, li_);
            g_Xh[off + lane]      = *(__nv_bfloat16*)&hr;
            g_Xh[off + 32 + lane] = *(__nv_bfloat16*)&hi_;
            g_Xl[off + lane]      = *(__nv_bfloat16*)&lr;
            g_Xl[off + 32 + lane] = *(__nv_bfloat16*)&li_;
            float npr = pr * lbr - pi * lbi;
            float npi = pr * lbi + pi * lbr;
            pr = npr; pi = npi;
        }
    }
}

// ---------------- GEMM2: y = X @ W2 + D.u  (coalesced smem-staged epilogue) ----
// 256 thr, BM=128, BN=128, K=64; grid (16, 128); warp = m32 x n64.
// Smem: Ah 16K | Al 16K | Bh 16K | Bl 16K for MMA; then reused as 128x132 fp32
// staging tile (67584 B) for the epilogue.
#define G2_PITCH 132
#define G2_SMEM  (128 * G2_PITCH * 4)   // 67584
__global__ __launch_bounds__(256) void k_gemm2(const float* __restrict__ u,
                                               const float* __restrict__ Dv,
                                               float* __restrict__ y) {
    extern __shared__ char smem[];
    char* pAh = smem;
    char* pAl = smem + 16384;
    char* pBh = smem + 32768;
    char* pBl = smem + 49152;
    int tid = threadIdx.x;
    int lane = tid & 31, g = lane >> 2, tig = lane & 3;
    int w = tid >> 5, wm = w >> 1, wn = w & 1;
    int n0 = blockIdx.x * 128;
    int m0 = blockIdx.y * 128;

    #pragma unroll
    for (int i = 0; i < 4; ++i) {
        int task = tid + 256 * i;
        int row = task >> 3, kp = task & 7;
        size_t goff = ((size_t)(m0 + row) * N2 + kp * 8) * 2;
        int off = kp * 2048 + ((row ^ kp) << 4);
        *(uint4*)(pAh + off) = *(const uint4*)((const char*)g_Xh + goff);
        *(uint4*)(pAl + off) = *(const uint4*)((const char*)g_Xl + goff);
    }
    #pragma unroll
    for (int i = 0; i < 4; ++i) {
        int task = tid + 256 * i;
        int n = task >> 3, kp = task & 7;
        size_t goff = ((size_t)(n0 + n) * N2 + kp * 8) * 2;
        int off = kp * 2048 + ((n ^ kp) << 4);
        *(uint4*)(pBh + off) = *(const uint4*)((const char*)g_W2h + goff);
        *(uint4*)(pBl + off) = *(const uint4*)((const char*)g_W2l + goff);
    }
    __syncthreads();

    float acc[2][8][4];
    #pragma unroll
    for (int mt = 0; mt < 2; ++mt)
        #pragma unroll
        for (int f = 0; f < 8; ++f)
            #pragma unroll
            for (int i = 0; i < 4; ++i) acc[mt][f][i] = 0.f;

    uint32_t aBh = smem_u32(pBh), aBl = smem_u32(pBl);
    uint32_t aAh = smem_u32(pAh), aAl = smem_u32(pAl);

    #pragma unroll
    for (int ks = 0; ks < 4; ++ks) {
        int p = ks * 2;
        uint32_t ah0[4], ah1[4], al0[4], al1[4];
        ldsm4(aAh + lmoff(p, wm * 32,      lane, 2048), ah0);
        ldsm4(aAh + lmoff(p, wm * 32 + 16, lane, 2048), ah1);
        ldsm4(aAl + lmoff(p, wm * 32,      lane, 2048), al0);
        ldsm4(aAl + lmoff(p, wm * 32 + 16, lane, 2048), al1);
        uint32_t bh[16], bl[16];
        #pragma unroll
        for (int s = 0; s < 4; ++s) {
            ldsm4(aBh + lmoff(p, wn * 64 + s * 16, lane, 2048), bh + 4 * s);
            ldsm4(aBl + lmoff(p, wn * 64 + s * 16, lane, 2048), bl + 4 * s);
        }
        #pragma unroll
        for (int f = 0; f < 8; ++f) {
            int q = (f >> 1) * 4 + (f & 1);
            uint32_t bfh[2] = { bh[q], bh[q + 2] };
            uint32_t bfl[2] = { bl[q], bl[q + 2] };
            mma16816(acc[0][f], ah0, bfh);
            mma16816(acc[0][f], ah0, bfl);
            mma16816(acc[0][f], al0, bfh);
            mma16816(acc[1][f], ah1, bfh);
            mma16816(acc[1][f], ah1, bfl);
            mma16816(acc[1][f], al1, bfh);
        }
    }

    // epilogue: stage acc in smem, then fully coalesced y writes
    __syncthreads();                       // all LDSM reads done; reuse smem
    float* stg = (float*)smem;             // [128][G2_PITCH]
    #pragma unroll
    for (int f = 0; f < 8; ++f) {
        int col = wn * 64 + f * 8 + 2 * tig;
        #pragma unroll
        for (int mt = 0; mt < 2; ++mt) {
            int r0 = wm * 32 + mt * 16 + g;
            float* a = acc[mt][f];
            *(float2*)(stg + r0 * G2_PITCH + col)       = make_float2(a[0], a[1]);
            *(float2*)(stg + (r0 + 8) * G2_PITCH + col) = make_float2(a[2], a[3]);
        }
    }
    __syncthreads();
    {
        float4 dv = *(const float4*)(Dv + n0 + lane * 4);
        int rbase = w * 16;
        #pragma unroll
        for (int r = 0; r < 16; ++r) {
            int row = rbase + r;
            float4 a = *(const float4*)(stg + row * G2_PITCH + lane * 4);
            size_t o = (size_t)(m0 + row) * DMODEL + n0 + lane * 4;
            float4 uu = *(const float4*)(u + o);
            float4 out;
            out.x = a.x + dv.x * uu.x;
            out.y = a.y + dv.y * uu.y;
            out.z = a.z + dv.z * uu.z;
            out.w = a.w + dv.w * uu.w;
            *(float4*)(y + o) = out;
        }
    }
}

// ---------------- launch ----------------
extern "C" void kernel_launch(void* const* d_in, const int* in_sizes, int n_in,
                              void* d_out, int out_size) {
    const float* u    = (const float*)d_in[0];
    const float* Lur  = (const float*)d_in[1];
    const float* Lim  = (const float*)d_in[2];
    const float* Bre  = (const float*)d_in[3];
    const float* Bim  = (const float*)d_in[4];
    const float* Cre  = (const float*)d_in[5];
    const float* Cim  = (const float*)d_in[6];
    const float* Dv   = (const float*)d_in[7];
    const float* logD = (const float*)d_in[8];
    float* y = (float*)d_out;

    const int g1_bytes = 2 * G1_STAGE;   // 98304
    const int g2_bytes = G2_SMEM;        // 67584
    cudaFuncSetAttribute(k_gemm1, cudaFuncAttributeMaxDynamicSharedMemorySize,
                         g1_bytes);
    cudaFuncSetAttribute(k_gemm2, cudaFuncAttributeMaxDynamicSharedMemorySize,
                         g2_bytes);

    k_wprep<<<128, 256>>>(Lur, Lim, logD, Bre, Bim, Cre, Cim);
    k_gemm1<<<MTOT / 128, 256, g1_bytes>>>(u);
    k_scan<<<BATCH, 1024>>>(Lur, Lim, logD);
    k_gemm2<<<dim3(DMODEL / 128, MTOT / 128), 256, g2_bytes>>>(u, Dv, y);
}